// round 5
// baseline (speedup 1.0000x reference)
#include <cuda_runtime.h>
#include <cuda_fp16.h>
#include <cstdint>

#define NB      1024
#define NN      256
#define ITERS   100
#define EPSD    1e-8f
#define THREADS 512

// padded K layout: 256 rows x 264 halves (528 B row stride)
#define ROWB    528

// smem byte offsets
#define OFF_KS   0                 // 256*264*2 = 135168
#define OFF_UH   135168            // 256 half
#define OFF_VH   135680            // 256 half
#define OFF_US   136192            // 256 f32
#define OFF_VS   137216
#define OFF_AS   138240
#define OFF_BS   139264
#define OFF_RED  140288            // 16 f32
#define SMEM_BYTES 140352

__device__ float g_batch_cost[NB];

__device__ __forceinline__ uint32_t smem_u32(const void* p) {
    uint32_t r;
    asm("{ .reg .u64 t; cvta.to.shared.u64 t, %1; cvt.u32.u64 %0, t; }" : "=r"(r) : "l"(p));
    return r;
}

__device__ __forceinline__ void ldsm_x4(uint32_t& r0, uint32_t& r1, uint32_t& r2,
                                        uint32_t& r3, uint32_t addr) {
    asm volatile("ldmatrix.sync.aligned.m8n8.x4.shared.b16 {%0,%1,%2,%3}, [%4];"
                 : "=r"(r0), "=r"(r1), "=r"(r2), "=r"(r3) : "r"(addr));
}

__device__ __forceinline__ void ldsm_x4_trans(uint32_t& r0, uint32_t& r1, uint32_t& r2,
                                              uint32_t& r3, uint32_t addr) {
    asm volatile("ldmatrix.sync.aligned.m8n8.x4.trans.shared.b16 {%0,%1,%2,%3}, [%4];"
                 : "=r"(r0), "=r"(r1), "=r"(r2), "=r"(r3) : "r"(addr));
}

__device__ __forceinline__ void mma16816(float c[4], uint32_t a0, uint32_t a1,
                                         uint32_t a2, uint32_t a3,
                                         uint32_t b0, uint32_t b1) {
    asm volatile(
        "mma.sync.aligned.m16n8k16.row.col.f32.f16.f16.f32 "
        "{%0,%1,%2,%3}, {%4,%5,%6,%7}, {%8,%9}, {%0,%1,%2,%3};"
        : "+f"(c[0]), "+f"(c[1]), "+f"(c[2]), "+f"(c[3])
        : "r"(a0), "r"(a1), "r"(a2), "r"(a3), "r"(b0), "r"(b1));
}

// exp(-10*c) = 2^(-10*log2e*c), deg-5 poly, rel err ~2.4e-6
__device__ __forceinline__ float fast_exp_n10(float c) {
    float t = c * (-14.426950408889634f);
    float r = rintf(t);
    float f = t - r;
    float p = 1.3333558146e-3f;
    p = fmaf(p, f, 9.6181291076e-3f);
    p = fmaf(p, f, 5.5504108664e-2f);
    p = fmaf(p, f, 2.4022650696e-1f);
    p = fmaf(p, f, 6.9314718056e-1f);
    p = fmaf(p, f, 1.0f);
    return __int_as_float(__float_as_int(p) + (((int)r) << 23));
}

__device__ __forceinline__ float block_reduce(float val, float* red, int t) {
    #pragma unroll
    for (int o = 16; o > 0; o >>= 1)
        val += __shfl_xor_sync(0xffffffffu, val, o);
    if ((t & 31) == 0) red[t >> 5] = val;
    __syncthreads();
    if (t < 32) {
        float v2 = (t < (THREADS / 32)) ? red[t] : 0.0f;
        #pragma unroll
        for (int o = 8; o > 0; o >>= 1)
            v2 += __shfl_xor_sync(0xffffffffu, v2, o);
        if (t == 0) red[0] = v2;
    }
    __syncthreads();
    float out = red[0];
    __syncthreads();
    return out;
}

__global__ void __launch_bounds__(THREADS, 1)
sinkhorn_main(const float* __restrict__ Cmat,
              const float* __restrict__ mp,
              const float* __restrict__ mt) {
    extern __shared__ __align__(16) char A0[];
    __half* uh  = (__half*)(A0 + OFF_UH);
    __half* vh  = (__half*)(A0 + OFF_VH);
    float*  u_s = (float*)(A0 + OFF_US);
    float*  v_s = (float*)(A0 + OFF_VS);
    float*  a_s = (float*)(A0 + OFF_AS);
    float*  b_s = (float*)(A0 + OFF_BS);
    float*  red = (float*)(A0 + OFF_RED);

    const int t    = threadIdx.x;
    const int lane = t & 31;
    const int w    = t >> 5;              // warp 0..15
    const int b    = blockIdx.x;
    const float* Cb = Cmat + (size_t)b * (NN * NN);
    const uint32_t ks_base = smem_u32(A0 + OFF_KS);

    // ---- build K = exp(-C/eps) fp16 into padded row-major smem ----
    {
        const float4* C4 = (const float4*)Cb;
        for (int i = t; i < (NN * NN / 4); i += THREADS) {
            float4 c4 = C4[i];
            int n = i >> 6;
            int m = (i & 63) << 2;
            __half2 h0 = __floats2half2_rn(fast_exp_n10(c4.x), fast_exp_n10(c4.y));
            __half2 h1 = __floats2half2_rn(fast_exp_n10(c4.z), fast_exp_n10(c4.w));
            uint2 kk;
            kk.x = *(uint32_t*)&h0;
            kk.y = *(uint32_t*)&h1;
            *(uint2*)(A0 + OFF_KS + n * ROWB + m * 2) = kk;
        }
    }

    // ---- normalize masses (block_reduce syncs also cover K writes) ----
    float mpv = (t < NN) ? mp[b * NN + t] : 0.0f;
    float mtv = (t < NN) ? mt[b * NN + t] : 0.0f;
    float smp = block_reduce(mpv, red, t);
    float smt = block_reduce(mtv, red, t);
    if (t < NN) {
        a_s[t] = mpv / (smp + EPSD);
        b_s[t] = mtv / (smt + EPSD);
        u_s[t] = 1.0f;
        uh[t]  = __float2half_rn(1.0f);
    }
    __syncthreads();

    // ---- one-time: A-fragments of K^T into registers ----
    // warp w owns output m-rows [w*16, w*16+16); ka[kc*4..+3] = A-frag for
    // (m rows = w*16..+16, k = n in [kc*16,+16)) of K^T, via ldmatrix.trans on K.
    uint32_t ka[64];
    {
        const uint32_t trow = (uint32_t)((lane & 16) ? 8 : 0) + (uint32_t)(lane & 7);
        const uint32_t tcol = (uint32_t)(w * 16 + ((lane & 8) ? 8 : 0)) * 2;
        #pragma unroll
        for (int kc = 0; kc < 16; ++kc) {
            uint32_t addr = ks_base + ((uint32_t)kc * 16 + trow) * ROWB + tcol;
            ldsm_x4_trans(ka[kc * 4], ka[kc * 4 + 1], ka[kc * 4 + 2], ka[kc * 4 + 3], addr);
        }
    }

    const int lm2 = (lane & 3) * 2;   // k-pair base within 16-chunk
    const uint32_t lrowB = ks_base + (uint32_t)(w * 16 + (lane & 15)) * ROWB
                         + ((lane & 16) ? 16u : 0u);
    const int r0 = w * 16 + (lane >> 2);   // output row for epilogues

    for (int it = 0; it < ITERS; ++it) {
        // ===== Phase A: Ktu[m] = sum_n K^T[m,n]*u[n]; A-frags in regs =====
        float accA[2][4] = {{0,0,0,0},{0,0,0,0}};
        #pragma unroll
        for (int kc = 0; kc < 16; ++kc) {
            uint32_t b0 = *(const uint32_t*)(uh + kc * 16 + lm2);
            uint32_t b1 = *(const uint32_t*)(uh + kc * 16 + lm2 + 8);
            mma16816(accA[kc & 1], ka[kc * 4], ka[kc * 4 + 1],
                     ka[kc * 4 + 2], ka[kc * 4 + 3], b0, b1);
        }
        if ((lane & 3) == 0) {
            float s0 = accA[0][0] + accA[1][0];
            float s8 = accA[0][2] + accA[1][2];
            float v0 = __fdividef(b_s[r0],     s0 + EPSD);
            float v8 = __fdividef(b_s[r0 + 8], s8 + EPSD);
            v_s[r0]     = v0;
            v_s[r0 + 8] = v8;
            vh[r0]     = __float2half_rn(v0);
            vh[r0 + 8] = __float2half_rn(v8);
        }
        __syncthreads();

        // ===== Phase B: Kv[n] = sum_m K[n,m]*v[m]; warp w rows [w*16,+16) =====
        float accB[2][4] = {{0,0,0,0},{0,0,0,0}};
        #pragma unroll
        for (int kc = 0; kc < 16; ++kc) {
            uint32_t b0 = *(const uint32_t*)(vh + kc * 16 + lm2);
            uint32_t b1 = *(const uint32_t*)(vh + kc * 16 + lm2 + 8);
            uint32_t A0r, A1r, A2r, A3r;
            ldsm_x4(A0r, A1r, A2r, A3r, lrowB + (uint32_t)kc * 32);
            mma16816(accB[kc & 1], A0r, A1r, A2r, A3r, b0, b1);
        }
        if ((lane & 3) == 0) {
            float s0 = accB[0][0] + accB[1][0];
            float s8 = accB[0][2] + accB[1][2];
            float u0 = __fdividef(a_s[r0],     s0 + EPSD);
            float u8 = __fdividef(a_s[r0 + 8], s8 + EPSD);
            u_s[r0]     = u0;
            u_s[r0 + 8] = u8;
            uh[r0]     = __float2half_rn(u0);
            uh[r0 + 8] = __float2half_rn(u8);
        }
        __syncthreads();
    }

    // ===== final cost: sum_nm u[n]*K[n,m]*v[m]*C[n,m] =====
    float csum = 0.0f;
    {
        const float4* C4 = (const float4*)Cb;
        for (int i = t; i < (NN * NN / 4); i += THREADS) {
            float4 c4 = C4[i];
            int n = i >> 6;
            int m = (i & 63) << 2;
            uint2 kk = *(const uint2*)(A0 + OFF_KS + n * ROWB + m * 2);
            float2 f0 = __half22float2(*(__half2*)&kk.x);
            float2 f1 = __half22float2(*(__half2*)&kk.y);
            float4 vv = *(const float4*)(v_s + m);
            float un = u_s[n];
            float e = f0.x * vv.x * c4.x;
            e = fmaf(f0.y * vv.y, c4.y, e);
            e = fmaf(f1.x * vv.z, c4.z, e);
            e = fmaf(f1.y * vv.w, c4.w, e);
            csum = fmaf(un, e, csum);
        }
    }
    float tot = block_reduce(csum, red, t);
    if (t == 0) g_batch_cost[b] = tot;
}

// deterministic final mean over batches
__global__ void sinkhorn_reduce(float* __restrict__ out) {
    __shared__ float sm[256];
    const int t = threadIdx.x;
    float s = 0.0f;
    #pragma unroll
    for (int i = t; i < NB; i += 256) s += g_batch_cost[i];
    sm[t] = s;
    __syncthreads();
    #pragma unroll
    for (int k = 128; k > 0; k >>= 1) {
        if (t < k) sm[t] += sm[t + k];
        __syncthreads();
    }
    if (t == 0) out[0] = sm[0] * (1.0f / (float)NB);
}

extern "C" void kernel_launch(void* const* d_in, const int* in_sizes, int n_in,
                              void* d_out, int out_size) {
    (void)in_sizes; (void)n_in; (void)out_size;
    const float* C  = (const float*)d_in[0];
    const float* mp = (const float*)d_in[1];
    const float* mt = (const float*)d_in[2];
    float* out = (float*)d_out;

    cudaFuncSetAttribute(sinkhorn_main,
                         cudaFuncAttributeMaxDynamicSharedMemorySize, SMEM_BYTES);
    sinkhorn_main<<<NB, THREADS, SMEM_BYTES>>>(C, mp, mt);
    sinkhorn_reduce<<<1, 256>>>(out);
}

// round 6
// speedup vs baseline: 1.4978x; 1.4978x over previous
#include <cuda_runtime.h>
#include <cuda_fp16.h>
#include <cstdint>

#define NB      1024
#define NN      256
#define ITERS   100
#define EPSD    1e-8f
#define THREADS 512

// padded K layout: 256 rows x 264 halves (528 B row stride)
#define ROWB    528

// smem byte offsets
#define OFF_KS   0                 // 256*264*2 = 135168
#define OFF_UH   135168            // 256 half
#define OFF_VH   135680            // 256 half
#define OFF_US   136192            // 256 f32
#define OFF_VS   137216
#define OFF_AS   138240
#define OFF_BS   139264
#define OFF_RED  140288            // 16 f32
#define SMEM_BYTES 140352

__device__ float g_batch_cost[NB];

__device__ __forceinline__ uint32_t smem_u32(const void* p) {
    uint32_t r;
    asm("{ .reg .u64 t; cvta.to.shared.u64 t, %1; cvt.u32.u64 %0, t; }" : "=r"(r) : "l"(p));
    return r;
}

__device__ __forceinline__ void ldsm_x4(uint32_t& r0, uint32_t& r1, uint32_t& r2,
                                        uint32_t& r3, uint32_t addr) {
    asm volatile("ldmatrix.sync.aligned.m8n8.x4.shared.b16 {%0,%1,%2,%3}, [%4];"
                 : "=r"(r0), "=r"(r1), "=r"(r2), "=r"(r3) : "r"(addr));
}

__device__ __forceinline__ void ldsm_x4_trans(uint32_t& r0, uint32_t& r1, uint32_t& r2,
                                              uint32_t& r3, uint32_t addr) {
    asm volatile("ldmatrix.sync.aligned.m8n8.x4.trans.shared.b16 {%0,%1,%2,%3}, [%4];"
                 : "=r"(r0), "=r"(r1), "=r"(r2), "=r"(r3) : "r"(addr));
}

__device__ __forceinline__ void mma16816(float c[4], uint32_t a0, uint32_t a1,
                                         uint32_t a2, uint32_t a3,
                                         uint32_t b0, uint32_t b1) {
    asm volatile(
        "mma.sync.aligned.m16n8k16.row.col.f32.f16.f16.f32 "
        "{%0,%1,%2,%3}, {%4,%5,%6,%7}, {%8,%9}, {%0,%1,%2,%3};"
        : "+f"(c[0]), "+f"(c[1]), "+f"(c[2]), "+f"(c[3])
        : "r"(a0), "r"(a1), "r"(a2), "r"(a3), "r"(b0), "r"(b1));
}

// exp(-10*c) = 2^(-10*log2e*c), deg-5 poly, rel err ~2.4e-6
__device__ __forceinline__ float fast_exp_n10(float c) {
    float t = c * (-14.426950408889634f);
    float r = rintf(t);
    float f = t - r;
    float p = 1.3333558146e-3f;
    p = fmaf(p, f, 9.6181291076e-3f);
    p = fmaf(p, f, 5.5504108664e-2f);
    p = fmaf(p, f, 2.4022650696e-1f);
    p = fmaf(p, f, 6.9314718056e-1f);
    p = fmaf(p, f, 1.0f);
    return __int_as_float(__float_as_int(p) + (((int)r) << 23));
}

__device__ __forceinline__ float block_reduce(float val, float* red, int t) {
    #pragma unroll
    for (int o = 16; o > 0; o >>= 1)
        val += __shfl_xor_sync(0xffffffffu, val, o);
    if ((t & 31) == 0) red[t >> 5] = val;
    __syncthreads();
    if (t < 32) {
        float v2 = (t < (THREADS / 32)) ? red[t] : 0.0f;
        #pragma unroll
        for (int o = 8; o > 0; o >>= 1)
            v2 += __shfl_xor_sync(0xffffffffu, v2, o);
        if (t == 0) red[0] = v2;
    }
    __syncthreads();
    float out = red[0];
    __syncthreads();
    return out;
}

__global__ void __launch_bounds__(THREADS, 1)
sinkhorn_main(const float* __restrict__ Cmat,
              const float* __restrict__ mp,
              const float* __restrict__ mt) {
    extern __shared__ __align__(16) char A0[];
    __half* uh  = (__half*)(A0 + OFF_UH);
    __half* vh  = (__half*)(A0 + OFF_VH);
    float*  u_s = (float*)(A0 + OFF_US);
    float*  v_s = (float*)(A0 + OFF_VS);
    float*  a_s = (float*)(A0 + OFF_AS);
    float*  b_s = (float*)(A0 + OFF_BS);
    float*  red = (float*)(A0 + OFF_RED);

    const int t    = threadIdx.x;
    const int lane = t & 31;
    const int w    = t >> 5;              // warp 0..15
    const int b    = blockIdx.x;
    const float* Cb = Cmat + (size_t)b * (NN * NN);
    const uint32_t ks_base = smem_u32(A0 + OFF_KS);

    // ---- build K = exp(-C/eps) fp16 into padded row-major smem ----
    {
        const float4* C4 = (const float4*)Cb;
        for (int i = t; i < (NN * NN / 4); i += THREADS) {
            float4 c4 = C4[i];
            int n = i >> 6;
            int m = (i & 63) << 2;
            __half2 h0 = __floats2half2_rn(fast_exp_n10(c4.x), fast_exp_n10(c4.y));
            __half2 h1 = __floats2half2_rn(fast_exp_n10(c4.z), fast_exp_n10(c4.w));
            uint2 kk;
            kk.x = *(uint32_t*)&h0;
            kk.y = *(uint32_t*)&h1;
            *(uint2*)(A0 + OFF_KS + n * ROWB + m * 2) = kk;
        }
    }

    // ---- normalize masses (block_reduce syncs also cover K writes) ----
    float mpv = (t < NN) ? mp[b * NN + t] : 0.0f;
    float mtv = (t < NN) ? mt[b * NN + t] : 0.0f;
    float smp = block_reduce(mpv, red, t);
    float smt = block_reduce(mtv, red, t);
    if (t < NN) {
        a_s[t] = mpv / (smp + EPSD);
        b_s[t] = mtv / (smt + EPSD);
        u_s[t] = 1.0f;
        uh[t]  = __float2half_rn(1.0f);
    }
    __syncthreads();

    // ---- one-time: A-fragments of K^T into registers ----
    // warp w owns output m-rows [w*16, w*16+16); ka[kc*4..+3] = A-frag for
    // (m rows = w*16..+16, k = n in [kc*16,+16)) of K^T, via ldmatrix.trans on K.
    uint32_t ka[64];
    {
        const uint32_t trow = (uint32_t)((lane & 16) ? 8 : 0) + (uint32_t)(lane & 7);
        const uint32_t tcol = (uint32_t)(w * 16 + ((lane & 8) ? 8 : 0)) * 2;
        #pragma unroll
        for (int kc = 0; kc < 16; ++kc) {
            uint32_t addr = ks_base + ((uint32_t)kc * 16 + trow) * ROWB + tcol;
            ldsm_x4_trans(ka[kc * 4], ka[kc * 4 + 1], ka[kc * 4 + 2], ka[kc * 4 + 3], addr);
        }
    }

    const int lm2 = (lane & 3) * 2;   // k-pair base within 16-chunk
    const uint32_t lrowB = ks_base + (uint32_t)(w * 16 + (lane & 15)) * ROWB
                         + ((lane & 16) ? 16u : 0u);
    const int r0 = w * 16 + (lane >> 2);   // output row for epilogues

    for (int it = 0; it < ITERS; ++it) {
        // ===== Phase A: Ktu[m] = sum_n K^T[m,n]*u[n]; A-frags in regs =====
        // 4 independent accumulator chains (depth 4) to keep HMMA pipe full
        float accA[4][4] = {{0,0,0,0},{0,0,0,0},{0,0,0,0},{0,0,0,0}};
        #pragma unroll
        for (int kc = 0; kc < 16; ++kc) {
            uint32_t b0 = *(const uint32_t*)(uh + kc * 16 + lm2);
            uint32_t b1 = *(const uint32_t*)(uh + kc * 16 + lm2 + 8);
            mma16816(accA[kc & 3], ka[kc * 4], ka[kc * 4 + 1],
                     ka[kc * 4 + 2], ka[kc * 4 + 3], b0, b1);
        }
        if ((lane & 3) == 0) {
            float s0 = (accA[0][0] + accA[1][0]) + (accA[2][0] + accA[3][0]);
            float s8 = (accA[0][2] + accA[1][2]) + (accA[2][2] + accA[3][2]);
            float v0 = __fdividef(b_s[r0],     s0 + EPSD);
            float v8 = __fdividef(b_s[r0 + 8], s8 + EPSD);
            v_s[r0]     = v0;
            v_s[r0 + 8] = v8;
            vh[r0]     = __float2half_rn(v0);
            vh[r0 + 8] = __float2half_rn(v8);
        }
        __syncthreads();

        // ===== Phase B: Kv[n] = sum_m K[n,m]*v[m]; warp w rows [w*16,+16) =====
        float accB[4][4] = {{0,0,0,0},{0,0,0,0},{0,0,0,0},{0,0,0,0}};
        #pragma unroll
        for (int kc = 0; kc < 16; ++kc) {
            uint32_t b0 = *(const uint32_t*)(vh + kc * 16 + lm2);
            uint32_t b1 = *(const uint32_t*)(vh + kc * 16 + lm2 + 8);
            uint32_t A0r, A1r, A2r, A3r;
            ldsm_x4(A0r, A1r, A2r, A3r, lrowB + (uint32_t)kc * 32);
            mma16816(accB[kc & 3], A0r, A1r, A2r, A3r, b0, b1);
        }
        if ((lane & 3) == 0) {
            float s0 = (accB[0][0] + accB[1][0]) + (accB[2][0] + accB[3][0]);
            float s8 = (accB[0][2] + accB[1][2]) + (accB[2][2] + accB[3][2]);
            float u0 = __fdividef(a_s[r0],     s0 + EPSD);
            float u8 = __fdividef(a_s[r0 + 8], s8 + EPSD);
            u_s[r0]     = u0;
            u_s[r0 + 8] = u8;
            uh[r0]     = __float2half_rn(u0);
            uh[r0 + 8] = __float2half_rn(u8);
        }
        __syncthreads();
    }

    // ===== final cost: sum_nm u[n]*K[n,m]*v[m]*C[n,m] =====
    float csum = 0.0f;
    {
        const float4* C4 = (const float4*)Cb;
        for (int i = t; i < (NN * NN / 4); i += THREADS) {
            float4 c4 = C4[i];
            int n = i >> 6;
            int m = (i & 63) << 2;
            uint2 kk = *(const uint2*)(A0 + OFF_KS + n * ROWB + m * 2);
            float2 f0 = __half22float2(*(__half2*)&kk.x);
            float2 f1 = __half22float2(*(__half2*)&kk.y);
            float4 vv = *(const float4*)(v_s + m);
            float un = u_s[n];
            float e = f0.x * vv.x * c4.x;
            e = fmaf(f0.y * vv.y, c4.y, e);
            e = fmaf(f1.x * vv.z, c4.z, e);
            e = fmaf(f1.y * vv.w, c4.w, e);
            csum = fmaf(un, e, csum);
        }
    }
    float tot = block_reduce(csum, red, t);
    if (t == 0) g_batch_cost[b] = tot;
}

// deterministic final mean over batches
__global__ void sinkhorn_reduce(float* __restrict__ out) {
    __shared__ float sm[256];
    const int t = threadIdx.x;
    float s = 0.0f;
    #pragma unroll
    for (int i = t; i < NB; i += 256) s += g_batch_cost[i];
    sm[t] = s;
    __syncthreads();
    #pragma unroll
    for (int k = 128; k > 0; k >>= 1) {
        if (t < k) sm[t] += sm[t + k];
        __syncthreads();
    }
    if (t == 0) out[0] = sm[0] * (1.0f / (float)NB);
}

extern "C" void kernel_launch(void* const* d_in, const int* in_sizes, int n_in,
                              void* d_out, int out_size) {
    (void)in_sizes; (void)n_in; (void)out_size;
    const float* C  = (const float*)d_in[0];
    const float* mp = (const float*)d_in[1];
    const float* mt = (const float*)d_in[2];
    float* out = (float*)d_out;

    cudaFuncSetAttribute(sinkhorn_main,
                         cudaFuncAttributeMaxDynamicSharedMemorySize, SMEM_BYTES);
    sinkhorn_main<<<NB, THREADS, SMEM_BYTES>>>(C, mp, mt);
    sinkhorn_reduce<<<1, 256>>>(out);
}